// round 15
// baseline (speedup 1.0000x reference)
#include <cuda_runtime.h>
#include <cuda_fp16.h>

#define NUM_CU 100000
#define NUM_CI 50000
#define DIM 64
#define NUM_LAYERS 3
#define NUM_EDGES 1600000
#define EPS 1e-8f

#define TILE 1024
#define NT_U ((NUM_CU + TILE - 1) / TILE)   // 98
#define NT_I ((NUM_CI + TILE - 1) / TILE)   // 49
#define NT_TOT (NT_U + NT_I)                // 147  (<= 148 SMs: all resident)

#define BT 256
#define BT_PROP 128
#define G_EDGE2 (NUM_EDGES / 2 / BT)                      // 3125 edge blocks (2 edges/thread)
#define G_INIT4 ((NUM_CU + NUM_CI) * 16 / BT)             // 9375 init blocks (float4 granularity)
#define G_EI    (G_EDGE2 + G_INIT4)                       // 12500 (=4*G_EDGE2: interleave 1-in-4)

#define DEG_SCALE 4294967296.0             // 2^32 fixed-point for packed degree
#define CNT_ONE   (1ull << 48)
#define DEG_MASK  ((1ull << 48) - 1)

// ---------------- scratch (device globals; no allocation allowed) ----------------
__device__ unsigned g_rank[NUM_EDGES];           // {rank_u:16 | rank_i:16}
__device__ unsigned long long g_acc_u[NUM_CU];   // [count:16 | deg_fixed:48]  (self-zeroed by scan)
__device__ unsigned long long g_acc_i[NUM_CI];
__device__ int   g_off_u[NUM_CU + 1];
__device__ int   g_off_i[NUM_CI + 1];
__device__ int2  g_meta_u[NUM_CU];               // {bucket offset, rsqrt(deg+EPS) bits}
__device__ int2  g_meta_i[NUM_CI];
__device__ int   g_part[NT_TOT];
__device__ int   g_flag[NT_TOT];                 // self-zeroed by bucket
__device__ int2  g_bu[NUM_EDGES];                // user buckets: {item_idx, norm bits}
__device__ int2  g_bi[NUM_EDGES];                // item buckets: {user_idx, norm bits}
// fp16 layer embeddings: slot L holds layer-L output (32 half2/node = 128 B)
__device__ __align__(16) __half2 g_uh[3][NUM_CU * 32];
__device__ __align__(16) __half2 g_ih[3][NUM_CI * 32];

__device__ __forceinline__ float softplus_eps(float x) {
    return (x > 0.f ? x + log1pf(expf(-x)) : log1pf(expf(x))) + EPS;
}

__device__ __forceinline__ unsigned h2_bits(__half2 h) {
    __half2_raw r = h;
    return (unsigned)r.x | ((unsigned)r.y << 16);
}

// ---------------- kernels ----------------

// Fused edge + init kernel; edge blocks interleaved 1-in-4 so the L2-atomic
// stream stays co-resident with the DRAM init stream for the whole kernel.
__global__ void edge_init_kernel(const float* __restrict__ logit,
                                 const int* __restrict__ cu,
                                 const int* __restrict__ ci,
                                 const float* __restrict__ user_w,
                                 const float* __restrict__ item_w,
                                 const float* __restrict__ user_d,
                                 const float* __restrict__ item_d) {
    int b = blockIdx.x;
    if ((b & 3) == 0) {
        // ---- edge part: 2 edges per thread, 1 packed u64 atomic per side ----
        int eb = b >> 2;                                   // 0..G_EDGE2-1
        int e0 = (eb * BT + threadIdx.x) * 2;
        float x0 = logit[e0], x1 = logit[e0 + 1];
        int a0 = cu[e0], a1 = cu[e0 + 1];
        int b0 = ci[e0], b1 = ci[e0 + 1];
        float w0 = softplus_eps(x0);
        float w1 = softplus_eps(x1);
        unsigned long long p0 = CNT_ONE | (unsigned long long)((double)w0 * DEG_SCALE);
        unsigned long long p1 = CNT_ONE | (unsigned long long)((double)w1 * DEG_SCALE);
        unsigned long long ru0 = atomicAdd(&g_acc_u[a0], p0);
        unsigned long long ru1 = atomicAdd(&g_acc_u[a1], p1);
        unsigned long long ri0 = atomicAdd(&g_acc_i[b0], p0);
        unsigned long long ri1 = atomicAdd(&g_acc_i[b1], p1);
        uint2 pk;
        pk.x = (unsigned)(ru0 >> 48) | ((unsigned)(ri0 >> 48) << 16);
        pk.y = (unsigned)(ru1 >> 48) | ((unsigned)(ri1 >> 48) << 16);
        *(uint2*)&g_rank[e0] = pk;
    } else {
        // ---- init part: float4 granularity (4 floats = 2 half2 per thread) ----
        int ib = b - (b >> 2) - 1;                         // 0..G_INIT4-1
        int i = ib * BT + threadIdx.x;                     // float4 index
        const int NU4 = NUM_CU * 16;
        const float4* wsrc; const float4* dsrc; uint2* dst; int j;
        if (i < NU4) {
            wsrc = (const float4*)user_w; dsrc = (const float4*)user_d;
            dst = (uint2*)g_uh[0]; j = i;
        } else {
            wsrc = (const float4*)item_w; dsrc = (const float4*)item_d;
            dst = (uint2*)g_ih[0]; j = i - NU4;
        }
        float4 w = wsrc[j];
        float4 d = dsrc[j];
        __half2 h0 = __float22half2_rn(make_float2(w.x + d.x, w.y + d.y));
        __half2 h1 = __float22half2_rn(make_float2(w.z + d.z, w.w + d.w));
        uint2 pk;
        pk.x = h2_bits(h0);
        pk.y = h2_bits(h1);
        dst[j] = pk;
    }
}

// Single-kernel segmented exclusive scan with decoupled lookback.
// Emits per-node meta {offset, rsqrt(deg+EPS)}; self-zeroes g_acc for the
// next graph replay (consumed exactly once here).
__global__ __launch_bounds__(TILE) void scan_kernel() {
    int b = blockIdx.x;
    unsigned long long* acc; int* off; int2* meta; int n; int tile; int segStart;
    if (b < NT_U) { acc = g_acc_u; off = g_off_u; meta = g_meta_u; n = NUM_CU; tile = b;        segStart = 0;    }
    else          { acc = g_acc_i; off = g_off_i; meta = g_meta_i; n = NUM_CI; tile = b - NT_U; segStart = NT_U; }

    int tid = threadIdx.x;
    int lane = tid & 31, wid = tid >> 5;
    int i = tile * TILE + tid;
    unsigned long long a = 0ull;
    if (i < n) {
        a = acc[i];
        acc[i] = 0ull;                      // self-clean for next replay
    }
    int v = (int)(a >> 48);
    float deg = (float)((double)(a & DEG_MASK) * (1.0 / DEG_SCALE));

    __shared__ int ws[32];
    __shared__ int s_total;
    __shared__ int s_base;

    int x = v;
    #pragma unroll
    for (int d = 1; d < 32; d <<= 1) {
        int y = __shfl_up_sync(0xffffffffu, x, d);
        if (lane >= d) x += y;
    }
    if (lane == 31) ws[wid] = x;
    __syncthreads();
    if (wid == 0) {
        int wv = ws[lane];
        int xs = wv;
        #pragma unroll
        for (int d = 1; d < 32; d <<= 1) {
            int y = __shfl_up_sync(0xffffffffu, xs, d);
            if (lane >= d) xs += y;
        }
        ws[lane] = xs - wv;
        if (lane == 31) s_total = xs;
    }
    __syncthreads();
    int excl_blk = ws[wid] + (x - v);

    if (tid == 0) {
        g_part[b] = s_total;
        __threadfence();
        ((volatile int*)g_flag)[b] = 1;
    }
    if (wid == 0) {
        int np = b - segStart;
        int acc2 = 0;
        for (int j = lane; j < np; j += 32) {
            while (((volatile int*)g_flag)[segStart + j] == 0) { }
            acc2 += ((volatile int*)g_part)[segStart + j];
        }
        #pragma unroll
        for (int d = 16; d > 0; d >>= 1) acc2 += __shfl_down_sync(0xffffffffu, acc2, d);
        if (lane == 0) s_base = acc2;
    }
    __syncthreads();
    int base = s_base;
    if (i < n) {
        int o = base + excl_blk;
        off[i] = o;
        meta[i] = make_int2(o, __float_as_int(rsqrtf(deg + EPS)));
    }
    if (tid == 0 && (b == NT_U - 1 || b == NT_TOT - 1)) off[n] = base + s_total;
}

// Atomic-free bucket scatter: per edge, 2 random 8B meta reads + 2 random 8B
// stores. Block 0 also re-zeroes the scan lookback flags for the next replay.
__global__ void bucket_kernel(const float* __restrict__ logit,
                              const int* __restrict__ cu,
                              const int* __restrict__ ci) {
    if (blockIdx.x == 0 && threadIdx.x < NT_TOT) g_flag[threadIdx.x] = 0;
    int e = blockIdx.x * blockDim.x + threadIdx.x;
    if (e >= NUM_EDGES) return;
    int a = cu[e], b = ci[e];
    float w = softplus_eps(logit[e]);
    unsigned r = g_rank[e];
    int2 mu = g_meta_u[a];
    int2 mi = g_meta_i[b];
    float nr = w * __int_as_float(mu.y) * __int_as_float(mi.y);
    int nb = __float_as_int(nr);
    g_bu[mu.x + (int)(r & 0xFFFFu)] = make_int2(b, nb);
    g_bi[mi.x + (int)(r >> 16)]     = make_int2(a, nb);
}

// Fused both-direction propagation: warp per node, fp16 gather, fp32
// accumulate. 2-stage software pipeline over 4-edge batches: batch k+1's
// bucket entries load while batch k's gathers are in flight, removing the
// serial bucket->gather latency chain.
template <int P, bool LAST>
__global__ __launch_bounds__(BT_PROP) void prop_kernel(float* __restrict__ out) {
    int gw = (blockIdx.x * blockDim.x + threadIdx.x) >> 5;
    int lane = threadIdx.x & 31;
    if (gw >= NUM_CU + NUM_CI) return;

    const int2* __restrict__ bk;
    const __half2* __restrict__ src;
    __half2* __restrict__ dst;
    const __half2 *l0, *l1, *l2;
    float2* __restrict__ op;
    int n, s, t;
    if (gw < NUM_CU) {
        n = gw;
        s = g_off_u[n]; t = g_off_u[n + 1];
        bk = g_bu;
        src = g_ih[P];
        dst = LAST ? (__half2*)0 : g_uh[P + 1 < 3 ? P + 1 : 0];
        l0 = g_uh[0]; l1 = g_uh[1]; l2 = g_uh[2];
        op = (float2*)out;
    } else {
        n = gw - NUM_CU;
        s = g_off_i[n]; t = g_off_i[n + 1];
        bk = g_bi;
        src = g_uh[P];
        dst = LAST ? (__half2*)0 : g_ih[P + 1 < 3 ? P + 1 : 0];
        l0 = g_ih[0]; l1 = g_ih[1]; l2 = g_ih[2];
        op = (float2*)(out + NUM_CU * DIM);
    }

    int idx = n * 32 + lane;
    __half2 a0, a1, a2;
    if (LAST) {
        a0 = l0[idx]; a1 = l1[idx]; a2 = l2[idx];
    }

    float2 acc = make_float2(0.f, 0.f);
    int k = s;

    if (k + 4 <= t) {
        int2 e[4];
        #pragma unroll
        for (int j = 0; j < 4; ++j) e[j] = __ldg(&bk[k + j]);
        // steady state: gathers for e, prefetch next indices, then FMA
        while (k + 8 <= t) {
            __half2 h[4];
            #pragma unroll
            for (int j = 0; j < 4; ++j) h[j] = __ldg(&src[e[j].x * 32 + lane]);
            int2 en[4];
            #pragma unroll
            for (int j = 0; j < 4; ++j) en[j] = __ldg(&bk[k + 4 + j]);
            #pragma unroll
            for (int j = 0; j < 4; ++j) {
                float2 v = __half22float2(h[j]);
                float nr = __int_as_float(e[j].y);
                acc.x = fmaf(nr, v.x, acc.x);
                acc.y = fmaf(nr, v.y, acc.y);
            }
            #pragma unroll
            for (int j = 0; j < 4; ++j) e[j] = en[j];
            k += 4;
        }
        // drain the staged batch
        {
            __half2 h[4];
            #pragma unroll
            for (int j = 0; j < 4; ++j) h[j] = __ldg(&src[e[j].x * 32 + lane]);
            #pragma unroll
            for (int j = 0; j < 4; ++j) {
                float2 v = __half22float2(h[j]);
                float nr = __int_as_float(e[j].y);
                acc.x = fmaf(nr, v.x, acc.x);
                acc.y = fmaf(nr, v.y, acc.y);
            }
            k += 4;
        }
    }
    for (; k < t; ++k) {
        int2 e0 = __ldg(&bk[k]);
        float2 v0 = __half22float2(__ldg(&src[e0.x * 32 + lane]));
        float n0 = __int_as_float(e0.y);
        acc.x = fmaf(n0, v0.x, acc.x);
        acc.y = fmaf(n0, v0.y, acc.y);
    }

    if (LAST) {
        const float sc = 1.0f / (NUM_LAYERS + 1);
        float2 f0 = __half22float2(a0);
        float2 f1 = __half22float2(a1);
        float2 f2 = __half22float2(a2);
        float2 r;
        r.x = (f0.x + f1.x + f2.x + acc.x) * sc;
        r.y = (f0.y + f1.y + f2.y + acc.y) * sc;
        op[idx] = r;
    } else {
        dst[idx] = __float22half2_rn(acc);
    }
}

// ---------------- launch ----------------
extern "C" void kernel_launch(void* const* d_in, const int* in_sizes, int n_in,
                              void* d_out, int out_size) {
    const float* user_w     = (const float*)d_in[0];
    const float* item_w     = (const float*)d_in[1];
    const float* user_delta = (const float*)d_in[2];
    const float* item_delta = (const float*)d_in[3];
    const float* edge_logit = (const float*)d_in[4];
    const int*   cu         = (const int*)d_in[5];
    const int*   ci         = (const int*)d_in[6];
    float* out = (float*)d_out;

    int gEdges = (NUM_EDGES + BT - 1) / BT;
    int gProp  = ((NUM_CU + NUM_CI) * 32 + BT_PROP - 1) / BT_PROP;

    edge_init_kernel<<<G_EI, BT>>>(edge_logit, cu, ci,
                                   user_w, item_w, user_delta, item_delta);
    scan_kernel<<<NT_TOT, TILE>>>();
    bucket_kernel<<<gEdges, BT>>>(edge_logit, cu, ci);

    prop_kernel<0, false><<<gProp, BT_PROP>>>(out);
    prop_kernel<1, false><<<gProp, BT_PROP>>>(out);
    prop_kernel<2, true ><<<gProp, BT_PROP>>>(out);
}

// round 16
// speedup vs baseline: 1.0469x; 1.0469x over previous
#include <cuda_runtime.h>
#include <cuda_fp16.h>

#define NUM_CU 100000
#define NUM_CI 50000
#define DIM 64
#define NUM_LAYERS 3
#define NUM_EDGES 1600000
#define EPS 1e-8f

#define TILE 1024
#define NT_U ((NUM_CU + TILE - 1) / TILE)   // 98
#define NT_I ((NUM_CI + TILE - 1) / TILE)   // 49
#define NT_TOT (NT_U + NT_I)                // 147  (<= 148 SMs: all resident)

#define BT 256
#define BT_PROP 128
#define G_EDGE2 (NUM_EDGES / 2 / BT)                      // 3125 edge blocks (2 edges/thread)
#define G_INIT4 ((NUM_CU + NUM_CI) * 16 / BT)             // 9375 init blocks (float4 granularity)
#define G_EI    (G_EDGE2 + G_INIT4)                       // 12500 (=4*G_EDGE2: interleave 1-in-4)

#define DEG_SCALE 4294967296.0             // 2^32 fixed-point for packed degree
#define CNT_ONE   (1ull << 48)
#define DEG_MASK  ((1ull << 48) - 1)

// ---------------- scratch (device globals; no allocation allowed) ----------------
__device__ unsigned g_rank[NUM_EDGES];           // {rank_u:16 | rank_i:16}
__device__ unsigned long long g_acc_u[NUM_CU];   // [count:16 | deg_fixed:48]  (self-zeroed by scan)
__device__ unsigned long long g_acc_i[NUM_CI];
__device__ int   g_off_u[NUM_CU + 1];
__device__ int   g_off_i[NUM_CI + 1];
__device__ int2  g_meta_u[NUM_CU];               // {bucket offset, rsqrt(deg+EPS) bits}
__device__ int2  g_meta_i[NUM_CI];
__device__ int   g_part[NT_TOT];
__device__ int   g_flag[NT_TOT];                 // self-zeroed by bucket
__device__ int2  g_bu[NUM_EDGES];                // user buckets: {item_idx, norm bits}
__device__ int2  g_bi[NUM_EDGES];                // item buckets: {user_idx, norm bits}
// fp16 layer embeddings: slot L holds layer-L output (32 half2/node = 128 B)
__device__ __align__(16) __half2 g_uh[3][NUM_CU * 32];
__device__ __align__(16) __half2 g_ih[3][NUM_CI * 32];

__device__ __forceinline__ float softplus_eps(float x) {
    return (x > 0.f ? x + log1pf(expf(-x)) : log1pf(expf(x))) + EPS;
}

__device__ __forceinline__ unsigned h2_bits(__half2 h) {
    __half2_raw r = h;
    return (unsigned)r.x | ((unsigned)r.y << 16);
}

// ---------------- kernels ----------------

// Fused edge + init kernel; edge blocks interleaved 1-in-4 so the L2-atomic
// stream stays co-resident with the DRAM init stream for the whole kernel.
__global__ void edge_init_kernel(const float* __restrict__ logit,
                                 const int* __restrict__ cu,
                                 const int* __restrict__ ci,
                                 const float* __restrict__ user_w,
                                 const float* __restrict__ item_w,
                                 const float* __restrict__ user_d,
                                 const float* __restrict__ item_d) {
    int b = blockIdx.x;
    if ((b & 3) == 0) {
        // ---- edge part: 2 edges per thread, 1 packed u64 atomic per side ----
        int eb = b >> 2;                                   // 0..G_EDGE2-1
        int e0 = (eb * BT + threadIdx.x) * 2;
        float x0 = logit[e0], x1 = logit[e0 + 1];
        int a0 = cu[e0], a1 = cu[e0 + 1];
        int b0 = ci[e0], b1 = ci[e0 + 1];
        float w0 = softplus_eps(x0);
        float w1 = softplus_eps(x1);
        unsigned long long p0 = CNT_ONE | (unsigned long long)((double)w0 * DEG_SCALE);
        unsigned long long p1 = CNT_ONE | (unsigned long long)((double)w1 * DEG_SCALE);
        unsigned long long ru0 = atomicAdd(&g_acc_u[a0], p0);
        unsigned long long ru1 = atomicAdd(&g_acc_u[a1], p1);
        unsigned long long ri0 = atomicAdd(&g_acc_i[b0], p0);
        unsigned long long ri1 = atomicAdd(&g_acc_i[b1], p1);
        uint2 pk;
        pk.x = (unsigned)(ru0 >> 48) | ((unsigned)(ri0 >> 48) << 16);
        pk.y = (unsigned)(ru1 >> 48) | ((unsigned)(ri1 >> 48) << 16);
        *(uint2*)&g_rank[e0] = pk;
    } else {
        // ---- init part: float4 granularity (4 floats = 2 half2 per thread) ----
        int ib = b - (b >> 2) - 1;                         // 0..G_INIT4-1
        int i = ib * BT + threadIdx.x;                     // float4 index
        const int NU4 = NUM_CU * 16;
        const float4* wsrc; const float4* dsrc; uint2* dst; int j;
        if (i < NU4) {
            wsrc = (const float4*)user_w; dsrc = (const float4*)user_d;
            dst = (uint2*)g_uh[0]; j = i;
        } else {
            wsrc = (const float4*)item_w; dsrc = (const float4*)item_d;
            dst = (uint2*)g_ih[0]; j = i - NU4;
        }
        float4 w = wsrc[j];
        float4 d = dsrc[j];
        __half2 h0 = __float22half2_rn(make_float2(w.x + d.x, w.y + d.y));
        __half2 h1 = __float22half2_rn(make_float2(w.z + d.z, w.w + d.w));
        uint2 pk;
        pk.x = h2_bits(h0);
        pk.y = h2_bits(h1);
        dst[j] = pk;
    }
}

// Single-kernel segmented exclusive scan with decoupled lookback.
// Emits per-node meta {offset, rsqrt(deg+EPS)}; self-zeroes g_acc for the
// next graph replay (consumed exactly once here).
__global__ __launch_bounds__(TILE) void scan_kernel() {
    int b = blockIdx.x;
    unsigned long long* acc; int* off; int2* meta; int n; int tile; int segStart;
    if (b < NT_U) { acc = g_acc_u; off = g_off_u; meta = g_meta_u; n = NUM_CU; tile = b;        segStart = 0;    }
    else          { acc = g_acc_i; off = g_off_i; meta = g_meta_i; n = NUM_CI; tile = b - NT_U; segStart = NT_U; }

    int tid = threadIdx.x;
    int lane = tid & 31, wid = tid >> 5;
    int i = tile * TILE + tid;
    unsigned long long a = 0ull;
    if (i < n) {
        a = acc[i];
        acc[i] = 0ull;                      // self-clean for next replay
    }
    int v = (int)(a >> 48);
    float deg = (float)((double)(a & DEG_MASK) * (1.0 / DEG_SCALE));

    __shared__ int ws[32];
    __shared__ int s_total;
    __shared__ int s_base;

    int x = v;
    #pragma unroll
    for (int d = 1; d < 32; d <<= 1) {
        int y = __shfl_up_sync(0xffffffffu, x, d);
        if (lane >= d) x += y;
    }
    if (lane == 31) ws[wid] = x;
    __syncthreads();
    if (wid == 0) {
        int wv = ws[lane];
        int xs = wv;
        #pragma unroll
        for (int d = 1; d < 32; d <<= 1) {
            int y = __shfl_up_sync(0xffffffffu, xs, d);
            if (lane >= d) xs += y;
        }
        ws[lane] = xs - wv;
        if (lane == 31) s_total = xs;
    }
    __syncthreads();
    int excl_blk = ws[wid] + (x - v);

    if (tid == 0) {
        g_part[b] = s_total;
        __threadfence();
        ((volatile int*)g_flag)[b] = 1;
    }
    if (wid == 0) {
        int np = b - segStart;
        int acc2 = 0;
        for (int j = lane; j < np; j += 32) {
            while (((volatile int*)g_flag)[segStart + j] == 0) { }
            acc2 += ((volatile int*)g_part)[segStart + j];
        }
        #pragma unroll
        for (int d = 16; d > 0; d >>= 1) acc2 += __shfl_down_sync(0xffffffffu, acc2, d);
        if (lane == 0) s_base = acc2;
    }
    __syncthreads();
    int base = s_base;
    if (i < n) {
        int o = base + excl_blk;
        off[i] = o;
        meta[i] = make_int2(o, __float_as_int(rsqrtf(deg + EPS)));
    }
    if (tid == 0 && (b == NT_U - 1 || b == NT_TOT - 1)) off[n] = base + s_total;
}

// Atomic-free bucket scatter: per edge, 2 random 8B meta reads + 2 random 8B
// stores. Block 0 also re-zeroes the scan lookback flags for the next replay.
__global__ void bucket_kernel(const float* __restrict__ logit,
                              const int* __restrict__ cu,
                              const int* __restrict__ ci) {
    if (blockIdx.x == 0 && threadIdx.x < NT_TOT) g_flag[threadIdx.x] = 0;
    int e = blockIdx.x * blockDim.x + threadIdx.x;
    if (e >= NUM_EDGES) return;
    int a = cu[e], b = ci[e];
    float w = softplus_eps(logit[e]);
    unsigned r = g_rank[e];
    int2 mu = g_meta_u[a];
    int2 mi = g_meta_i[b];
    float nr = w * __int_as_float(mu.y) * __int_as_float(mi.y);
    int nb = __float_as_int(nr);
    g_bu[mu.x + (int)(r & 0xFFFFu)] = make_int2(b, nb);
    g_bi[mi.x + (int)(r >> 16)]     = make_int2(a, nb);
}

// Fused both-direction propagation: warp per node, fp16 gather, fp32 accumulate.
// Heavy item warps (avg deg 32) scheduled FIRST; light user warps (avg deg 16)
// fill the trailing waves — longest-processing-time-first tail reduction.
template <int P, bool LAST>
__global__ __launch_bounds__(BT_PROP) void prop_kernel(float* __restrict__ out) {
    int gw = (blockIdx.x * blockDim.x + threadIdx.x) >> 5;
    int lane = threadIdx.x & 31;
    if (gw >= NUM_CU + NUM_CI) return;

    const int2* __restrict__ bk;
    const __half2* __restrict__ src;
    __half2* __restrict__ dst;
    const __half2 *l0, *l1, *l2;
    float2* __restrict__ op;
    int n, s, t;
    if (gw < NUM_CI) {
        // item nodes first (heavier)
        n = gw;
        s = g_off_i[n]; t = g_off_i[n + 1];
        bk = g_bi;
        src = g_uh[P];
        dst = LAST ? (__half2*)0 : g_ih[P + 1 < 3 ? P + 1 : 0];
        l0 = g_ih[0]; l1 = g_ih[1]; l2 = g_ih[2];
        op = (float2*)(out + NUM_CU * DIM);
    } else {
        n = gw - NUM_CI;
        s = g_off_u[n]; t = g_off_u[n + 1];
        bk = g_bu;
        src = g_ih[P];
        dst = LAST ? (__half2*)0 : g_uh[P + 1 < 3 ? P + 1 : 0];
        l0 = g_uh[0]; l1 = g_uh[1]; l2 = g_uh[2];
        op = (float2*)out;
    }

    int idx = n * 32 + lane;
    __half2 a0, a1, a2;
    if (LAST) {
        a0 = l0[idx]; a1 = l1[idx]; a2 = l2[idx];
    }

    float2 acc = make_float2(0.f, 0.f);
    int k = s;
    for (; k + 8 <= t; k += 8) {
        int2 e[8];
        #pragma unroll
        for (int j = 0; j < 8; ++j) e[j] = __ldg(&bk[k + j]);
        __half2 h[8];
        #pragma unroll
        for (int j = 0; j < 8; ++j) h[j] = __ldg(&src[e[j].x * 32 + lane]);
        #pragma unroll
        for (int j = 0; j < 8; ++j) {
            float2 v = __half22float2(h[j]);
            float nr = __int_as_float(e[j].y);
            acc.x = fmaf(nr, v.x, acc.x);
            acc.y = fmaf(nr, v.y, acc.y);
        }
    }
    if (k + 4 <= t) {
        int2 e[4];
        #pragma unroll
        for (int j = 0; j < 4; ++j) e[j] = __ldg(&bk[k + j]);
        __half2 h[4];
        #pragma unroll
        for (int j = 0; j < 4; ++j) h[j] = __ldg(&src[e[j].x * 32 + lane]);
        #pragma unroll
        for (int j = 0; j < 4; ++j) {
            float2 v = __half22float2(h[j]);
            float nr = __int_as_float(e[j].y);
            acc.x = fmaf(nr, v.x, acc.x);
            acc.y = fmaf(nr, v.y, acc.y);
        }
        k += 4;
    }
    for (; k < t; ++k) {
        int2 e0 = __ldg(&bk[k]);
        float2 v0 = __half22float2(__ldg(&src[e0.x * 32 + lane]));
        float n0 = __int_as_float(e0.y);
        acc.x = fmaf(n0, v0.x, acc.x);
        acc.y = fmaf(n0, v0.y, acc.y);
    }

    if (LAST) {
        const float sc = 1.0f / (NUM_LAYERS + 1);
        float2 f0 = __half22float2(a0);
        float2 f1 = __half22float2(a1);
        float2 f2 = __half22float2(a2);
        float2 r;
        r.x = (f0.x + f1.x + f2.x + acc.x) * sc;
        r.y = (f0.y + f1.y + f2.y + acc.y) * sc;
        op[idx] = r;
    } else {
        dst[idx] = __float22half2_rn(acc);
    }
}

// ---------------- launch ----------------
extern "C" void kernel_launch(void* const* d_in, const int* in_sizes, int n_in,
                              void* d_out, int out_size) {
    const float* user_w     = (const float*)d_in[0];
    const float* item_w     = (const float*)d_in[1];
    const float* user_delta = (const float*)d_in[2];
    const float* item_delta = (const float*)d_in[3];
    const float* edge_logit = (const float*)d_in[4];
    const int*   cu         = (const int*)d_in[5];
    const int*   ci         = (const int*)d_in[6];
    float* out = (float*)d_out;

    int gEdges = (NUM_EDGES + BT - 1) / BT;
    int gProp  = ((NUM_CU + NUM_CI) * 32 + BT_PROP - 1) / BT_PROP;

    edge_init_kernel<<<G_EI, BT>>>(edge_logit, cu, ci,
                                   user_w, item_w, user_delta, item_delta);
    scan_kernel<<<NT_TOT, TILE>>>();
    bucket_kernel<<<gEdges, BT>>>(edge_logit, cu, ci);

    prop_kernel<0, false><<<gProp, BT_PROP>>>(out);
    prop_kernel<1, false><<<gProp, BT_PROP>>>(out);
    prop_kernel<2, true ><<<gProp, BT_PROP>>>(out);
}

// round 17
// speedup vs baseline: 1.0958x; 1.0467x over previous
#include <cuda_runtime.h>
#include <cuda_fp16.h>

#define NUM_CU 100000
#define NUM_CI 50000
#define DIM 64
#define NUM_LAYERS 3
#define NUM_EDGES 1600000
#define EPS 1e-8f

#define TILE 1024
#define NT_U ((NUM_CU + TILE - 1) / TILE)   // 98
#define NT_I ((NUM_CI + TILE - 1) / TILE)   // 49
#define NT_TOT (NT_U + NT_I)                // 147  (<= 148 SMs: all resident)

#define BT 256
#define BT_PROP 128
#define G_EDGE2 (NUM_EDGES / 2 / BT)                      // 3125 edge blocks (2 edges/thread)
#define G_INIT4 ((NUM_CU + NUM_CI) * 16 / BT)             // 9375 init blocks (float4 granularity)
#define G_EI    (G_EDGE2 + G_INIT4)                       // 12500 (=4*G_EDGE2: interleave 1-in-4)

#define DEG_SCALE 4294967296.0             // 2^32 fixed-point for packed degree
#define CNT_ONE   (1ull << 48)
#define DEG_MASK  ((1ull << 48) - 1)

// ---------------- scratch (device globals; no allocation allowed) ----------------
__device__ unsigned g_rank[NUM_EDGES];           // {rank_u:16 | rank_i:16}
__device__ unsigned long long g_acc_u[NUM_CU];   // [count:16 | deg_fixed:48]  (self-zeroed by scan)
__device__ unsigned long long g_acc_i[NUM_CI];
__device__ int   g_off_u[NUM_CU + 1];
__device__ int   g_off_i[NUM_CI + 1];
__device__ int2  g_meta_u[NUM_CU];               // {bucket offset, rsqrt(deg+EPS) bits}
__device__ int2  g_meta_i[NUM_CI];
__device__ int   g_part[NT_TOT];
__device__ int   g_flag[NT_TOT];                 // self-zeroed by bucket
__device__ int2  g_bu[NUM_EDGES];                // user buckets: {item_idx*32, norm bits}
__device__ int2  g_bi[NUM_EDGES];                // item buckets: {user_idx*32, norm bits}
// fp16 layer embeddings: slot L holds layer-L output (32 half2/node = 128 B)
__device__ __align__(16) __half2 g_uh[3][NUM_CU * 32];
__device__ __align__(16) __half2 g_ih[3][NUM_CI * 32];

__device__ __forceinline__ float softplus_eps(float x) {
    return (x > 0.f ? x + log1pf(expf(-x)) : log1pf(expf(x))) + EPS;
}

__device__ __forceinline__ unsigned h2_bits(__half2 h) {
    __half2_raw r = h;
    return (unsigned)r.x | ((unsigned)r.y << 16);
}

// ---------------- kernels ----------------

// Fused edge + init kernel; edge blocks interleaved 1-in-4 so the L2-atomic
// stream stays co-resident with the DRAM init stream for the whole kernel.
__global__ void edge_init_kernel(const float* __restrict__ logit,
                                 const int* __restrict__ cu,
                                 const int* __restrict__ ci,
                                 const float* __restrict__ user_w,
                                 const float* __restrict__ item_w,
                                 const float* __restrict__ user_d,
                                 const float* __restrict__ item_d) {
    int b = blockIdx.x;
    if ((b & 3) == 0) {
        // ---- edge part: 2 edges per thread, 1 packed u64 atomic per side ----
        int eb = b >> 2;                                   // 0..G_EDGE2-1
        int e0 = (eb * BT + threadIdx.x) * 2;
        float x0 = logit[e0], x1 = logit[e0 + 1];
        int a0 = cu[e0], a1 = cu[e0 + 1];
        int b0 = ci[e0], b1 = ci[e0 + 1];
        float w0 = softplus_eps(x0);
        float w1 = softplus_eps(x1);
        unsigned long long p0 = CNT_ONE | (unsigned long long)((double)w0 * DEG_SCALE);
        unsigned long long p1 = CNT_ONE | (unsigned long long)((double)w1 * DEG_SCALE);
        unsigned long long ru0 = atomicAdd(&g_acc_u[a0], p0);
        unsigned long long ru1 = atomicAdd(&g_acc_u[a1], p1);
        unsigned long long ri0 = atomicAdd(&g_acc_i[b0], p0);
        unsigned long long ri1 = atomicAdd(&g_acc_i[b1], p1);
        uint2 pk;
        pk.x = (unsigned)(ru0 >> 48) | ((unsigned)(ri0 >> 48) << 16);
        pk.y = (unsigned)(ru1 >> 48) | ((unsigned)(ri1 >> 48) << 16);
        *(uint2*)&g_rank[e0] = pk;
    } else {
        // ---- init part: float4 granularity (4 floats = 2 half2 per thread) ----
        int ib = b - (b >> 2) - 1;                         // 0..G_INIT4-1
        int i = ib * BT + threadIdx.x;                     // float4 index
        const int NU4 = NUM_CU * 16;
        const float4* wsrc; const float4* dsrc; uint2* dst; int j;
        if (i < NU4) {
            wsrc = (const float4*)user_w; dsrc = (const float4*)user_d;
            dst = (uint2*)g_uh[0]; j = i;
        } else {
            wsrc = (const float4*)item_w; dsrc = (const float4*)item_d;
            dst = (uint2*)g_ih[0]; j = i - NU4;
        }
        float4 w = wsrc[j];
        float4 d = dsrc[j];
        __half2 h0 = __float22half2_rn(make_float2(w.x + d.x, w.y + d.y));
        __half2 h1 = __float22half2_rn(make_float2(w.z + d.z, w.w + d.w));
        uint2 pk;
        pk.x = h2_bits(h0);
        pk.y = h2_bits(h1);
        dst[j] = pk;
    }
}

// Single-kernel segmented exclusive scan with decoupled lookback.
// Emits per-node meta {offset, rsqrt(deg+EPS)}; self-zeroes g_acc for the
// next graph replay (consumed exactly once here).
__global__ __launch_bounds__(TILE) void scan_kernel() {
    int b = blockIdx.x;
    unsigned long long* acc; int* off; int2* meta; int n; int tile; int segStart;
    if (b < NT_U) { acc = g_acc_u; off = g_off_u; meta = g_meta_u; n = NUM_CU; tile = b;        segStart = 0;    }
    else          { acc = g_acc_i; off = g_off_i; meta = g_meta_i; n = NUM_CI; tile = b - NT_U; segStart = NT_U; }

    int tid = threadIdx.x;
    int lane = tid & 31, wid = tid >> 5;
    int i = tile * TILE + tid;
    unsigned long long a = 0ull;
    if (i < n) {
        a = acc[i];
        acc[i] = 0ull;                      // self-clean for next replay
    }
    int v = (int)(a >> 48);
    float deg = (float)((double)(a & DEG_MASK) * (1.0 / DEG_SCALE));

    __shared__ int ws[32];
    __shared__ int s_total;
    __shared__ int s_base;

    int x = v;
    #pragma unroll
    for (int d = 1; d < 32; d <<= 1) {
        int y = __shfl_up_sync(0xffffffffu, x, d);
        if (lane >= d) x += y;
    }
    if (lane == 31) ws[wid] = x;
    __syncthreads();
    if (wid == 0) {
        int wv = ws[lane];
        int xs = wv;
        #pragma unroll
        for (int d = 1; d < 32; d <<= 1) {
            int y = __shfl_up_sync(0xffffffffu, xs, d);
            if (lane >= d) xs += y;
        }
        ws[lane] = xs - wv;
        if (lane == 31) s_total = xs;
    }
    __syncthreads();
    int excl_blk = ws[wid] + (x - v);

    if (tid == 0) {
        g_part[b] = s_total;
        __threadfence();
        ((volatile int*)g_flag)[b] = 1;
    }
    if (wid == 0) {
        int np = b - segStart;
        int acc2 = 0;
        for (int j = lane; j < np; j += 32) {
            while (((volatile int*)g_flag)[segStart + j] == 0) { }
            acc2 += ((volatile int*)g_part)[segStart + j];
        }
        #pragma unroll
        for (int d = 16; d > 0; d >>= 1) acc2 += __shfl_down_sync(0xffffffffu, acc2, d);
        if (lane == 0) s_base = acc2;
    }
    __syncthreads();
    int base = s_base;
    if (i < n) {
        int o = base + excl_blk;
        off[i] = o;
        meta[i] = make_int2(o, __float_as_int(rsqrtf(deg + EPS)));
    }
    if (tid == 0 && (b == NT_U - 1 || b == NT_TOT - 1)) off[n] = base + s_total;
}

// Atomic-free bucket scatter: per edge, 2 random 8B meta reads + 2 random 8B
// stores. Neighbor indices stored pre-scaled by 32 (half2 stride units).
// Block 0 also re-zeroes the scan lookback flags for the next replay.
__global__ void bucket_kernel(const float* __restrict__ logit,
                              const int* __restrict__ cu,
                              const int* __restrict__ ci) {
    if (blockIdx.x == 0 && threadIdx.x < NT_TOT) g_flag[threadIdx.x] = 0;
    int e = blockIdx.x * blockDim.x + threadIdx.x;
    if (e >= NUM_EDGES) return;
    int a = cu[e], b = ci[e];
    float w = softplus_eps(logit[e]);
    unsigned r = g_rank[e];
    int2 mu = g_meta_u[a];
    int2 mi = g_meta_i[b];
    float nr = w * __int_as_float(mu.y) * __int_as_float(mi.y);
    int nb = __float_as_int(nr);
    g_bu[mu.x + (int)(r & 0xFFFFu)] = make_int2(b << 5, nb);
    g_bi[mi.x + (int)(r >> 16)]     = make_int2(a << 5, nb);
}

// Fused both-direction propagation: warp per node, fp16 gather, fp32 accumulate.
// Heavy item warps first (LPT scheduling). Bucket indices pre-scaled: gather
// address is src + e.x + lane (no IMAD). LAST writes `out` with streaming
// stores to keep L2 for buckets/tables.
template <int P, bool LAST>
__global__ __launch_bounds__(BT_PROP) void prop_kernel(float* __restrict__ out) {
    int gw = (blockIdx.x * blockDim.x + threadIdx.x) >> 5;
    int lane = threadIdx.x & 31;
    if (gw >= NUM_CU + NUM_CI) return;

    const int2* __restrict__ bk;
    const __half2* __restrict__ src;
    __half2* __restrict__ dst;
    const __half2 *l0, *l1, *l2;
    float2* __restrict__ op;
    int n, s, t;
    if (gw < NUM_CI) {
        // item nodes first (heavier)
        n = gw;
        s = g_off_i[n]; t = g_off_i[n + 1];
        bk = g_bi;
        src = g_uh[P];
        dst = LAST ? (__half2*)0 : g_ih[P + 1 < 3 ? P + 1 : 0];
        l0 = g_ih[0]; l1 = g_ih[1]; l2 = g_ih[2];
        op = (float2*)(out + NUM_CU * DIM);
    } else {
        n = gw - NUM_CI;
        s = g_off_u[n]; t = g_off_u[n + 1];
        bk = g_bu;
        src = g_ih[P];
        dst = LAST ? (__half2*)0 : g_uh[P + 1 < 3 ? P + 1 : 0];
        l0 = g_uh[0]; l1 = g_uh[1]; l2 = g_uh[2];
        op = (float2*)out;
    }
    const __half2* srcl = src + lane;    // lane folded into base

    int idx = n * 32 + lane;
    __half2 a0, a1, a2;
    if (LAST) {
        a0 = l0[idx]; a1 = l1[idx]; a2 = l2[idx];
    }

    float2 acc = make_float2(0.f, 0.f);
    int k = s;
    for (; k + 8 <= t; k += 8) {
        int2 e[8];
        #pragma unroll
        for (int j = 0; j < 8; ++j) e[j] = __ldg(&bk[k + j]);
        __half2 h[8];
        #pragma unroll
        for (int j = 0; j < 8; ++j) h[j] = __ldg(&srcl[e[j].x]);
        #pragma unroll
        for (int j = 0; j < 8; ++j) {
            float2 v = __half22float2(h[j]);
            float nr = __int_as_float(e[j].y);
            acc.x = fmaf(nr, v.x, acc.x);
            acc.y = fmaf(nr, v.y, acc.y);
        }
    }
    if (k + 4 <= t) {
        int2 e[4];
        #pragma unroll
        for (int j = 0; j < 4; ++j) e[j] = __ldg(&bk[k + j]);
        __half2 h[4];
        #pragma unroll
        for (int j = 0; j < 4; ++j) h[j] = __ldg(&srcl[e[j].x]);
        #pragma unroll
        for (int j = 0; j < 4; ++j) {
            float2 v = __half22float2(h[j]);
            float nr = __int_as_float(e[j].y);
            acc.x = fmaf(nr, v.x, acc.x);
            acc.y = fmaf(nr, v.y, acc.y);
        }
        k += 4;
    }
    for (; k < t; ++k) {
        int2 e0 = __ldg(&bk[k]);
        float2 v0 = __half22float2(__ldg(&srcl[e0.x]));
        float n0 = __int_as_float(e0.y);
        acc.x = fmaf(n0, v0.x, acc.x);
        acc.y = fmaf(n0, v0.y, acc.y);
    }

    if (LAST) {
        const float sc = 1.0f / (NUM_LAYERS + 1);
        float2 f0 = __half22float2(a0);
        float2 f1 = __half22float2(a1);
        float2 f2 = __half22float2(a2);
        float2 r;
        r.x = (f0.x + f1.x + f2.x + acc.x) * sc;
        r.y = (f0.y + f1.y + f2.y + acc.y) * sc;
        __stcs(&op[idx], r);             // streaming: out never re-read
    } else {
        dst[idx] = __float22half2_rn(acc);
    }
}

// ---------------- launch ----------------
extern "C" void kernel_launch(void* const* d_in, const int* in_sizes, int n_in,
                              void* d_out, int out_size) {
    const float* user_w     = (const float*)d_in[0];
    const float* item_w     = (const float*)d_in[1];
    const float* user_delta = (const float*)d_in[2];
    const float* item_delta = (const float*)d_in[3];
    const float* edge_logit = (const float*)d_in[4];
    const int*   cu         = (const int*)d_in[5];
    const int*   ci         = (const int*)d_in[6];
    float* out = (float*)d_out;

    int gEdges = (NUM_EDGES + BT - 1) / BT;
    int gProp  = ((NUM_CU + NUM_CI) * 32 + BT_PROP - 1) / BT_PROP;

    edge_init_kernel<<<G_EI, BT>>>(edge_logit, cu, ci,
                                   user_w, item_w, user_delta, item_delta);
    scan_kernel<<<NT_TOT, TILE>>>();
    bucket_kernel<<<gEdges, BT>>>(edge_logit, cu, ci);

    prop_kernel<0, false><<<gProp, BT_PROP>>>(out);
    prop_kernel<1, false><<<gProp, BT_PROP>>>(out);
    prop_kernel<2, true ><<<gProp, BT_PROP>>>(out);
}